// round 17
// baseline (speedup 1.0000x reference)
#include <cuda_runtime.h>
#include <cuda_bf16.h>
#include <math.h>
#include <cstdint>

#define BB   128
#define TSEQ 512
#define DD   256
#define HH   256
#define NG   1024
#define NBLK 96

typedef unsigned long long u64;
typedef unsigned int u32;

// ---- warp-level bf16 MMA ----
__device__ __forceinline__ void mma_bf16(float* c, u32 a0, u32 a1, u32 a2, u32 a3,
                                         u32 b0, u32 b1) {
    asm volatile(
        "mma.sync.aligned.m16n8k16.row.col.f32.bf16.bf16.f32 "
        "{%0,%1,%2,%3}, {%4,%5,%6,%7}, {%8,%9}, {%0,%1,%2,%3};"
        : "+f"(c[0]), "+f"(c[1]), "+f"(c[2]), "+f"(c[3])
        : "r"(a0), "r"(a1), "r"(a2), "r"(a3), "r"(b0), "r"(b1));
}
__device__ __forceinline__ u32 smem_u32addr(const void* p) {
    u32 a;
    asm("{ .reg .u64 t; cvta.to.shared.u64 t, %1; cvt.u32.u64 %0, t; }" : "=r"(a) : "l"(p));
    return a;
}
__device__ __forceinline__ void cp_async16(u32 dst, const void* src) {
    asm volatile("cp.async.cg.shared.global [%0], [%1], 16;" :: "r"(dst), "l"(src));
}
#define CP_COMMIT() asm volatile("cp.async.commit_group;" ::: "memory")
#define CP_WAIT0()  asm volatile("cp.async.wait_group 0;" ::: "memory")
__device__ __forceinline__ float tanha(float x) {
    float r; asm("tanh.approx.f32 %0, %1;" : "=f"(r) : "f"(x)); return r;
}
__device__ __forceinline__ float sigm(float x) {
    return 0.5f + 0.5f * tanha(0.5f * x);
}

// ---------------- device scratch ----------------
__device__ float g_x[BB * TSEQ * DD];
__device__ float g_feats[BB * TSEQ * DD];
__device__ float g_h[2 * 3 * 2 * BB * HH];
__device__ float g_c[2 * 3 * BB * HH];
__device__ unsigned g_done[6 * TSEQ];       // dataflow counters [dl][t]
__device__ u32 g_xh2[BB * TSEQ * 128];
__device__ u32 g_xl2[BB * TSEQ * 128];
__device__ u32 g_Wb2[2 * 15 * 2 * 32768];
__device__ __nv_bfloat16 g_Wlb[2ull * 6 * 1024 * 512];
__device__ __nv_bfloat16 g_hbh[6 * 2 * BB * 256];
__device__ __nv_bfloat16 g_hbl[6 * 2 * BB * 256];
__device__ __nv_bfloat16 g_cbh[2 * 2 * 2 * BB * 256];
__device__ __nv_bfloat16 g_cbl[2 * 2 * 2 * BB * 256];

// ---------------- embedding gather ----------------
__global__ void k_embed(const int* __restrict__ tokens, const float* __restrict__ E) {
    int row = blockIdx.x;
    int tok = tokens[row];
    const float4* src = reinterpret_cast<const float4*>(E) + (size_t)tok * (DD / 4);
    float4* dst = reinterpret_cast<float4*>(g_x) + (size_t)row * (DD / 4);
    dst[threadIdx.x] = src[threadIdx.x];
}

// ---------------- conv W pack ----------------
__global__ void k_wprep(const float* __restrict__ W3, const float* __restrict__ W5,
                        const float* __restrict__ W7) {
    int idx = blockIdx.x * 256 + threadIdx.x;
    const int TOT = 2 * 15 * 2 * 65536;
    if (idx >= TOT) return;
    int k     = idx & 255;
    int n     = (idx >> 8) & 255;
    int plane = (idx >> 16) & 1;
    int tp    = idx >> 17;
    int tap   = tp % 15;
    int iter  = tp / 15;
    const float* Wsrc; int kk, KW;
    if (tap < 3)      { Wsrc = W3; kk = tap;     KW = 3; }
    else if (tap < 8) { Wsrc = W5; kk = tap - 3; KW = 5; }
    else              { Wsrc = W7; kk = tap - 8; KW = 7; }
    float v = Wsrc[(((size_t)iter * KW + kk) * 256 + k) * 256 + n];
    __nv_bfloat16 hi = __float2bfloat16(v);
    __nv_bfloat16 val = plane ? __float2bfloat16(v - __bfloat162float(hi)) : hi;
    __nv_bfloat16* dst = reinterpret_cast<__nv_bfloat16*>(g_Wb2);
    dst[(size_t)(((iter * 15 + tap) * 2 + plane)) * 65536 + n * 256 + k] = val;
}

// ---------------- LSTM W pack ----------
__global__ void k_wprep_lstm(const float* __restrict__ Wx, const float* __restrict__ Wh) {
    size_t idx = (size_t)blockIdx.x * 256 + threadIdx.x;
    const size_t TOT = 2ull * 6 * 1024 * 512;
    if (idx >= TOT) return;
    int k     = (int)(idx & 511);
    int n     = (int)((idx >> 9) & 1023);
    int dl    = (int)((idx >> 19) % 6);
    int plane = (int)(idx / (6ull << 19));
    int col = n >> 2, g = n & 3;
    int nc = g * 256 + col;
    float v = (k < 256) ? Wx[(size_t)dl * 256 * NG + (size_t)k * NG + nc]
                        : Wh[(size_t)dl * 256 * NG + (size_t)(k - 256) * NG + nc];
    __nv_bfloat16 hi = __float2bfloat16(v);
    __nv_bfloat16 val = plane ? __float2bfloat16(v - __bfloat162float(hi)) : hi;
    g_Wlb[idx] = val;
}

// ---------------- x split ----------
__global__ void k_xsplit() {
    size_t idx = (size_t)blockIdx.x * 256 + threadIdx.x;
    float a0 = g_x[idx * 2], a1 = g_x[idx * 2 + 1];
    __nv_bfloat16 h0 = __float2bfloat16(a0), h1 = __float2bfloat16(a1);
    __nv_bfloat16 l0 = __float2bfloat16(a0 - __bfloat162float(h0));
    __nv_bfloat16 l1 = __float2bfloat16(a1 - __bfloat162float(h1));
    __nv_bfloat162 hp; hp.x = h0; hp.y = h1;
    __nv_bfloat162 lp; lp.x = l0; lp.y = l1;
    g_xh2[idx] = *reinterpret_cast<u32*>(&hp);
    g_xl2[idx] = *reinterpret_cast<u32*>(&lp);
}

// ---------------- conv bank on HMMA (split accumulators) ----------
#define CAP 132
#define SM_AL 9240
#define SM_B  18480
#define SM_CONV_U32 (18480 + 32768)
#define B_CHUNKS 4096
__global__ void __launch_bounds__(256, 1) k_conv_mma(
    const float* __restrict__ bconv, int iter)
{
    extern __shared__ u32 sm[];
    u32* Ah = sm;
    u32* Al = sm + SM_AL;
    u32* Bb = sm + SM_B;

    const int tid  = threadIdx.x;
    const int warp = tid >> 5, lane = tid & 31;
    const int gid  = lane >> 2, tg = lane & 3;
    const int b    = blockIdx.x >> 3;
    const int t0   = (blockIdx.x & 7) * 64;
    const int n0   = blockIdx.y * 64;
    const int wm   = (warp & 3) * 16;
    const int wn   = (warp >> 2) * 32;

    for (int idx = tid; idx < 70 * 128; idx += 256) {
        int r = idx >> 7, c = idx & 127;
        int t = t0 - 3 + r;
        u32 vh = 0, vl = 0;
        if (t >= 0 && t < TSEQ) {
            size_t g = ((size_t)b * TSEQ + t) * 128 + c;
            vh = g_xh2[g]; vl = g_xl2[g];
        }
        Ah[r * CAP + c] = vh;
        Al[r * CAP + c] = vl;
    }

    const size_t wbase = (size_t)(iter * 15) * 2 * 32768;
    {
        for (int i = tid; i < B_CHUNKS; i += 256) {
            int p = i >> 11, rem = i & 2047;
            int n = rem >> 5, cq = rem & 31;
            int c0 = cq * 4;
            u32 dsw = (u32)c0 ^ (((u32)n & 7) << 2);
            u32 dst = smem_u32addr(Bb + p * 8192 + n * 128 + dsw);
            const u32* src = g_Wb2 + wbase + (size_t)p * 32768 + (size_t)(n0 + n) * 128 + c0;
            cp_async16(dst, src);
        }
        CP_COMMIT();
    }
    CP_WAIT0();
    __syncthreads();

    float acc[3][4][4], accL[3][4][4];
#pragma unroll
    for (int w = 0; w < 3; ++w)
#pragma unroll
        for (int j = 0; j < 4; ++j)
#pragma unroll
            for (int q = 0; q < 4; ++q) { acc[w][j][q] = 0.f; accL[w][j][q] = 0.f; }

    for (int tap = 0; tap < 15; ++tap) {
        int widx, kk;
        if (tap < 3)      { widx = 0; kk = tap; }
        else if (tap < 8) { widx = 1; kk = tap - 3; }
        else              { widx = 2; kk = tap - 8; }
        const int shift = kk - widx - 1;
        const int buf = tap & 1;

        if (tap < 14) {
            const size_t nb = (size_t)((iter * 15 + tap + 1) * 2) * 32768;
            u32* Bo = Bb + (buf ^ 1) * 16384;
            for (int i = tid; i < B_CHUNKS; i += 256) {
                int p = i >> 11, rem = i & 2047;
                int n = rem >> 5, cq = rem & 31;
                int c0 = cq * 4;
                u32 dsw = (u32)c0 ^ (((u32)n & 7) << 2);
                u32 dst = smem_u32addr(Bo + p * 8192 + n * 128 + dsw);
                const u32* src = g_Wb2 + nb + (size_t)p * 32768 + (size_t)(n0 + n) * 128 + c0;
                cp_async16(dst, src);
            }
            CP_COMMIT();
        }

        const u32* Bh = Bb + buf * 16384;
        const u32* Bl = Bh + 8192;
        const int r0 = 3 + shift + wm + gid;
        const u32* arh0 = Ah + r0 * CAP;
        const u32* arh1 = arh0 + 8 * CAP;
        const u32* arl0 = Al + r0 * CAP;
        const u32* arl1 = arl0 + 8 * CAP;
        float* accw  = &acc[widx][0][0];
        float* accwL = &accL[widx][0][0];

#pragma unroll
        for (int ks = 0; ks < 16; ++ks) {
            const int kc2 = ks * 8;
            u32 ah0 = arh0[kc2 + tg],     ah1 = arh1[kc2 + tg];
            u32 ah2 = arh0[kc2 + tg + 4], ah3 = arh1[kc2 + tg + 4];
            u32 al0 = arl0[kc2 + tg],     al1 = arl1[kc2 + tg];
            u32 al2 = arl0[kc2 + tg + 4], al3 = arl1[kc2 + tg + 4];
#pragma unroll
            for (int j8 = 0; j8 < 4; ++j8) {
                int nl = wn + j8 * 8 + gid;
                u32 xr = ((u32)(nl & 7)) << 2;
                const u32* bhp = Bh + nl * 128;
                const u32* blp = Bl + nl * 128;
                u32 bh0 = bhp[(kc2 + tg) ^ xr];
                u32 bh1 = bhp[(kc2 + tg + 4) ^ xr];
                u32 bl0 = blp[(kc2 + tg) ^ xr];
                u32 bl1 = blp[(kc2 + tg + 4) ^ xr];
                mma_bf16(accw  + j8 * 4, ah0, ah1, ah2, ah3, bh0, bh1);
                mma_bf16(accwL + j8 * 4, ah0, ah1, ah2, ah3, bl0, bl1);
                mma_bf16(accw  + j8 * 4, al0, al1, al2, al3, bh0, bh1);
            }
        }

        if (tap < 14) {
            CP_WAIT0();
            __syncthreads();
        }
    }

    {
        const float* b3 = bconv + (iter * 3 + 0) * 256 + n0;
        const float* b5 = bconv + (iter * 3 + 1) * 256 + n0;
        const float* b7 = bconv + (iter * 3 + 2) * 256 + n0;
        const int trow = t0 + wm + gid;
#pragma unroll
        for (int j8 = 0; j8 < 4; ++j8) {
            int cl = wn + j8 * 8 + tg * 2;
            float bb3a = b3[cl], bb3b = b3[cl + 1];
            float bb5a = b5[cl], bb5b = b5[cl + 1];
            float bb7a = b7[cl], bb7b = b7[cl + 1];
#pragma unroll
            for (int rh = 0; rh < 2; ++rh) {
                size_t row = (size_t)b * TSEQ + trow + rh * 8;
                const float2 xv = *reinterpret_cast<const float2*>(
                    g_x + row * 256 + n0 + cl);
                float c3a = acc[0][j8][rh*2+0] + accL[0][j8][rh*2+0];
                float c3b = acc[0][j8][rh*2+1] + accL[0][j8][rh*2+1];
                float c5a = acc[1][j8][rh*2+0] + accL[1][j8][rh*2+0];
                float c5b = acc[1][j8][rh*2+1] + accL[1][j8][rh*2+1];
                float c7a = acc[2][j8][rh*2+0] + accL[2][j8][rh*2+0];
                float c7b = acc[2][j8][rh*2+1] + accL[2][j8][rh*2+1];
                float2 o;
                o.x = tanha(c3a + bb3a) + tanha(c5a + bb5a) + tanha(c7a + bb7a) + xv.x;
                o.y = tanha(c3b + bb3b) + tanha(c5b + bb5b) + tanha(c7b + bb7b) + xv.y;
                *reinterpret_cast<float2*>(g_feats + row * 256 + n0 + cl) = o;
            }
        }
    }
}

// ---------------- layernorm ----------------
__global__ void k_ln(const float* __restrict__ gamma, const float* __restrict__ beta, int iter) {
    int wid = threadIdx.x >> 5, lane = threadIdx.x & 31;
    int row = blockIdx.x * 8 + wid;
    const float4* f = reinterpret_cast<const float4*>(g_feats + (size_t)row * DD);
    float4 v0 = f[lane];
    float4 v1 = f[32 + lane];
    float s = v0.x + v0.y + v0.z + v0.w + v1.x + v1.y + v1.z + v1.w;
    float q = v0.x*v0.x + v0.y*v0.y + v0.z*v0.z + v0.w*v0.w +
              v1.x*v1.x + v1.y*v1.y + v1.z*v1.z + v1.w*v1.w;
#pragma unroll
    for (int ofs = 16; ofs; ofs >>= 1) {
        s += __shfl_xor_sync(0xffffffffu, s, ofs);
        q += __shfl_xor_sync(0xffffffffu, q, ofs);
    }
    float mean = s * (1.f / 256.f);
    float var  = q * (1.f / 256.f) - mean * mean;
    float rstd = rsqrtf(var + 1e-3f);

    const float* ga = gamma + iter * DD;
    const float* be = beta + iter * DD;
    float4* xo = reinterpret_cast<float4*>(g_x + (size_t)row * DD);
    int c0 = lane * 4;
    float4 r0, r1;
    r0.x = (v0.x - mean) * rstd * ga[c0 + 0] + be[c0 + 0];
    r0.y = (v0.y - mean) * rstd * ga[c0 + 1] + be[c0 + 1];
    r0.z = (v0.z - mean) * rstd * ga[c0 + 2] + be[c0 + 2];
    r0.w = (v0.w - mean) * rstd * ga[c0 + 3] + be[c0 + 3];
    r1.x = (v1.x - mean) * rstd * ga[128 + c0 + 0] + be[128 + c0 + 0];
    r1.y = (v1.y - mean) * rstd * ga[128 + c0 + 1] + be[128 + c0 + 1];
    r1.z = (v1.z - mean) * rstd * ga[128 + c0 + 2] + be[128 + c0 + 2];
    r1.w = (v1.w - mean) * rstd * ga[128 + c0 + 3] + be[128 + c0 + 3];
    xo[lane] = r0;
    xo[32 + lane] = r1;
}

__global__ void k_zero() {
    int i = blockIdx.x * 256 + threadIdx.x;
    if (i < 196608) {
        reinterpret_cast<u32*>(g_hbh)[i] = 0u;
        reinterpret_cast<u32*>(g_hbl)[i] = 0u;
    }
    if (i < 6 * TSEQ) g_done[i] = 0u;
}

// ---------------- persistent LSTM on HMMA, dataflow-synced chains ----------
// 96 blocks x 512 threads. Block (dl, sub): 16 col-tile, all 128 m, own t loop.
// Sync: g_done[dl][t] counts finished blocks (16 = chain step complete).
#define LAP 36
#define LSTM_SMEM_U32 (32768 + 2 * 2 * 128 * LAP)
__global__ void __launch_bounds__(512, 1) k_lstm_mma(
    const float* __restrict__ blstm, float* __restrict__ out)
{
    extern __shared__ u32 sm[];
    u32* Bs = sm;
    u32* As = sm + 32768;

    const int bx    = blockIdx.x;
    const int ls    = bx >> 4;
    const int dir   = ls & 1;
    const int layer = ls >> 1;
    const int sub   = bx & 15;
    const int j0    = sub * 16;
    const int tid   = threadIdx.x;
    const int warp  = tid >> 5, lane = tid & 31;
    const int gid   = lane >> 2, tg = lane & 3;
    const int mgrp  = warp & 7;
    const int ngrp  = warp >> 3;
    const int m0    = mgrp * 16;
    const int dl    = dir * 3 + layer;
    const int ci_res = j0 >> 6;

    for (int i = tid; i < 8192; i += 512) {
        int plane = i >> 12, rem = i & 4095;
        int n = rem >> 6, c0 = (rem & 63) * 4;
        u32 dsw = (u32)c0 ^ (((u32)n & 7) << 2);
        u32 dst = smem_u32addr(Bs + plane * 16384 + n * 256 + dsw);
        const __nv_bfloat16* src = g_Wlb +
            ((size_t)(plane * 6 + dl) * 1024 + (j0 * 4 + n)) * 512 + c0 * 2;
        cp_async16(dst, src);
    }
    CP_COMMIT();

    float bias[4][4];
    float creg[4];
#pragma unroll
    for (int j4 = 0; j4 < 4; ++j4) {
        int cg = j0 + 2 * (ngrp * 4 + j4) + (tg >> 1);
        bias[j4][0] = blstm[dl * NG + 0 * 256 + cg];
        bias[j4][1] = blstm[dl * NG + 1 * 256 + cg];
        bias[j4][2] = blstm[dl * NG + 2 * 256 + cg];
        bias[j4][3] = blstm[dl * NG + 3 * 256 + cg];
        creg[j4] = 0.f;
    }
    const int ftm = tid >> 2;
    const int fko = (tid & 3) * 16;
    const int mrow = m0 + gid + ((tg & 1) ? 8 : 0);

    CP_WAIT0();
    __syncthreads();

    for (int t = 0; t < TSEQ; ++t) {
        // ---- dataflow waits ----
        if (tid == 0) {
            if (t > 0) {
                volatile unsigned* p = &g_done[dl * TSEQ + (t - 1)];
                while (*p < 16u) { }
            }
            if (layer > 0) {
                volatile unsigned* p = &g_done[(dl - 1) * TSEQ + t];
                while (*p < 16u) { }
            }
            if (layer < 2 && t >= 2) {
                volatile unsigned* p = &g_done[(dl + 1) * TSEQ + (t - 2)];
                while (*p < 16u) { }
            }
        }
        __syncthreads();

        const int tt = dir ? (TSEQ - 1 - t) : t;
        const int rp = t & 1, wp = rp ^ 1;
        const int par = t & 1;
        const int lprev = (layer > 0) ? (layer - 1) : 0;
        const size_t curoffR = (size_t)((dir * 2 + lprev) * 2 + par) * BB * 256;
        const size_t curoffW = (size_t)((dir * 2 + layer) * 2 + par) * BB * 256;
        const size_t hoffR   = (size_t)(dl * 2 + rp) * BB * 256;
        const size_t hoffW   = (size_t)(dl * 2 + wp) * BB * 256;

        const __nv_bfloat16* gxh = reinterpret_cast<const __nv_bfloat16*>(g_xh2);
        const __nv_bfloat16* gxl = reinterpret_cast<const __nv_bfloat16*>(g_xl2);
        const __nv_bfloat16 *lowh, *lowl;
        if (layer == 0) {
            lowh = gxh + ((size_t)ftm * TSEQ + tt) * 256;
            lowl = gxl + ((size_t)ftm * TSEQ + tt) * 256;
        } else {
            lowh = g_cbh + curoffR + (size_t)ftm * 256;
            lowl = g_cbl + curoffR + (size_t)ftm * 256;
        }
        const __nv_bfloat16* hh_ = g_hbh + hoffR + (size_t)ftm * 256;
        const __nv_bfloat16* hl_ = g_hbl + hoffR + (size_t)ftm * 256;

        float ainv[4];
        float acc[4][4], accL[4][4];
#pragma unroll
        for (int j4 = 0; j4 < 4; ++j4)
#pragma unroll
            for (int q = 0; q < 4; ++q) { acc[j4][q] = 0.f; accL[j4][q] = 0.f; }

#define STAGE(ci_, buf_) do {                                              \
    int kb_ = (ci_) * 64 + fko;                                            \
    const __nv_bfloat16 *sh_, *sl_;                                        \
    if (kb_ < 256) { sh_ = lowh + kb_; sl_ = lowl + kb_; }                 \
    else           { sh_ = hh_ + (kb_ - 256); sl_ = hl_ + (kb_ - 256); }   \
    u32 db_ = (buf_) * (2 * 128 * LAP) + ftm * LAP + (fko >> 1);           \
    _Pragma("unroll")                                                      \
    for (int j_ = 0; j_ < 2; ++j_)                                         \
        cp_async16(smem_u32addr(As + db_ + j_ * 4), sh_ + j_ * 8);         \
    db_ += 128 * LAP;                                                      \
    _Pragma("unroll")                                                      \
    for (int j_ = 0; j_ < 2; ++j_)                                         \
        cp_async16(smem_u32addr(As + db_ + j_ * 4), sl_ + j_ * 8);         \
} while (0)

        STAGE(0, 0); CP_COMMIT(); CP_WAIT0(); __syncthreads();

        for (int ci = 0; ci < 8; ++ci) {
            if (ci < 7) { STAGE(ci + 1, (ci + 1) & 1); CP_COMMIT(); }

            const u32* AhB = As + (ci & 1) * (2 * 128 * LAP);
            const u32* AlB = AhB + 128 * LAP;
            const int ra = (m0 + gid) * LAP;
            const int rb = ra + 8 * LAP;
#pragma unroll
            for (int ks = 0; ks < 4; ++ks) {
                const int pk = ks * 8 + tg;
                const int kp = ci * 32 + pk;
                u32 ah0 = AhB[ra + pk],     ah1 = AhB[rb + pk];
                u32 ah2 = AhB[ra + pk + 4], ah3 = AhB[rb + pk + 4];
                u32 al0 = AlB[ra + pk],     al1 = AlB[rb + pk];
                u32 al2 = AlB[ra + pk + 4], al3 = AlB[rb + pk + 4];
#pragma unroll
                for (int j4 = 0; j4 < 4; ++j4) {
                    int nl = ngrp * 32 + j4 * 8 + gid;
                    u32 xr = (u32)(nl & 7) << 2;
                    const u32* bh = Bs + nl * 256;
                    const u32* bl = bh + 16384;
                    u32 b0h = bh[kp ^ xr], b1h = bh[(kp + 4) ^ xr];
                    u32 b0l = bl[kp ^ xr], b1l = bl[(kp + 4) ^ xr];
                    mma_bf16(acc[j4],  ah0, ah1, ah2, ah3, b0h, b1h);
                    mma_bf16(accL[j4], ah0, ah1, ah2, ah3, b0l, b1l);
                    mma_bf16(acc[j4],  al0, al1, al2, al3, b0h, b1h);
                }
            }

            if (ci == ci_res) {
#pragma unroll
                for (int j4 = 0; j4 < 4; ++j4) {
                    int cg = j0 + 2 * (ngrp * 4 + j4) + (tg >> 1);
                    int kc = cg - ci_res * 64;
                    u32 vh = AhB[mrow * LAP + (kc >> 1)];
                    u32 vl = AlB[mrow * LAP + (kc >> 1)];
                    __nv_bfloat162 bh2 = *reinterpret_cast<__nv_bfloat162*>(&vh);
                    __nv_bfloat162 bl2 = *reinterpret_cast<__nv_bfloat162*>(&vl);
                    float fh = __bfloat162float((kc & 1) ? bh2.y : bh2.x);
                    float fl = __bfloat162float((kc & 1) ? bl2.y : bl2.x);
                    ainv[j4] = fh + fl;
                }
            }

            if (ci < 7) { CP_WAIT0(); __syncthreads(); }
        }
#undef STAGE

        // ---- epilogue ----
#pragma unroll
        for (int j4 = 0; j4 < 4; ++j4) {
            float c0 = acc[j4][0] + accL[j4][0];
            float c1 = acc[j4][1] + accL[j4][1];
            float c2 = acc[j4][2] + accL[j4][2];
            float c3 = acc[j4][3] + accL[j4][3];
            float sendA = (tg & 1) ? c0 : c2;
            float sendB = (tg & 1) ? c1 : c3;
            float rA = __shfl_xor_sync(0xffffffffu, sendA, 1);
            float rB = __shfl_xor_sync(0xffffffffu, sendB, 1);
            float zi, zf, zg, zo;
            if (!(tg & 1)) { zi = c0; zf = c1; zg = rA; zo = rB; }
            else           { zi = rA; zf = rB; zg = c2; zo = c3; }
            zi += bias[j4][0]; zf += bias[j4][1];
            zg += bias[j4][2]; zo += bias[j4][3];
            float ig = sigm(zi);
            float fg = sigm(zf);
            float gg = tanha(zg);
            float og = sigm(zo);
            float cn = fg * creg[j4] + ig * gg;
            float hn = og * tanha(cn);
            creg[j4] = cn;
            int cg = j0 + 2 * (ngrp * 4 + j4) + (tg >> 1);
            size_t hidx = hoffW + (size_t)mrow * 256 + cg;
            __nv_bfloat16 hh2 = __float2bfloat16(hn);
            g_hbh[hidx] = hh2;
            g_hbl[hidx] = __float2bfloat16(hn - __bfloat162float(hh2));
            if (t == TSEQ - 1) {
                g_h[(size_t)(dl * 2 + wp) * BB * HH + (size_t)mrow * HH + cg] = hn;
                g_c[(size_t)dl * BB * HH + (size_t)mrow * HH + cg] = cn;
            }
            float cu = ainv[j4] + hn;
            if (layer == 2) {
                out[((size_t)mrow * TSEQ + tt) * 512 + dir * 256 + cg] = cu;
            } else {
                size_t cidx = curoffW + (size_t)mrow * 256 + cg;
                __nv_bfloat16 ch2 = __float2bfloat16(cu);
                g_cbh[cidx] = ch2;
                g_cbl[cidx] = __float2bfloat16(cu - __bfloat162float(ch2));
            }
        }

        // ---- signal completion of (dl, t) by this block ----
        __syncthreads();
        __threadfence();
        if (tid == 0) atomicAdd(&g_done[dl * TSEQ + t], 1u);
    }
}

// ---------------- final states ----------------
__global__ void k_states(float* __restrict__ out) {
    int idx = blockIdx.x * 256 + threadIdx.x;
    if (idx >= 2 * 3 * BB * HH) return;
    int j  = idx & 255;
    int m  = (idx >> 8) & 127;
    int dl = idx >> 15;
    const size_t SEQ = (size_t)BB * TSEQ * 512;
    const size_t SH  = 2 * 3 * BB * HH;
    out[SEQ + idx]      = g_h[(size_t)(dl * 2 + 0) * BB * HH + (size_t)m * HH + j];
    out[SEQ + SH + idx] = g_c[(size_t)dl * BB * HH + (size_t)m * HH + j];
}

// ---------------- launch ----------------
extern "C" void kernel_launch(void* const* d_in, const int* in_sizes, int n_in,
                              void* d_out, int out_size) {
    const int*   tokens = (const int*)d_in[0];
    const float* E      = (const float*)d_in[1];
    const float* W3     = (const float*)d_in[2];
    const float* W5     = (const float*)d_in[3];
    const float* W7     = (const float*)d_in[4];
    const float* bconv  = (const float*)d_in[5];
    const float* gamma  = (const float*)d_in[6];
    const float* beta   = (const float*)d_in[7];
    const float* Wx     = (const float*)d_in[8];
    const float* Wh     = (const float*)d_in[9];
    const float* blstm  = (const float*)d_in[10];
    float* out = (float*)d_out;

    const int SMEM_CONV = SM_CONV_U32 * 4;
    const int SMEM_LSTM = LSTM_SMEM_U32 * 4;
    static int s_attr = 0;
    if (!s_attr) {
        cudaFuncSetAttribute(k_conv_mma,
                             cudaFuncAttributeMaxDynamicSharedMemorySize, SMEM_CONV);
        cudaFuncSetAttribute(k_lstm_mma,
                             cudaFuncAttributeMaxDynamicSharedMemorySize, SMEM_LSTM);
        s_attr = 1;
    }

    k_embed<<<BB * TSEQ, 64>>>(tokens, E);
    k_wprep<<<(2 * 15 * 2 * 65536 + 255) / 256, 256>>>(W3, W5, W7);
    k_wprep_lstm<<<(int)((2ull * 6 * 1024 * 512 + 255) / 256), 256>>>(Wx, Wh);
    for (int it = 0; it < 2; ++it) {
        k_xsplit<<<(BB * TSEQ * 128) / 256, 256>>>();
        k_conv_mma<<<dim3(BB * 8, 4), 256, SMEM_CONV>>>(bconv, it);
        k_ln<<<BB * TSEQ / 8, 256>>>(gamma, beta, it);
    }
    k_xsplit<<<(BB * TSEQ * 128) / 256, 256>>>();
    k_zero<<<1536, 256>>>();
    k_lstm_mma<<<NBLK, 512, SMEM_LSTM>>>(blstm, out);
    k_states<<<768, 256>>>(out);
}